// round 7
// baseline (speedup 1.0000x reference)
#include <cuda_runtime.h>
#include <math.h>

#define TT   1024
#define DM   1024
#define NQ   16
#define NKV  4
#define DH   64
#define NB   63
#define TOPN 8
#define WIN  256
#define SCALE 0.125f

typedef unsigned long long ull;

// packed fp32x2 FMA: d = a*b + d  (per 32-bit half) -> SASS FFMA2
#define FMA2(d, a, b)  asm("fma.rn.f32x2 %0, %1, %2, %0;" : "+l"(d) : "l"(a), "l"(b))
// duplicate one float into both halves of a b64
#define PACKDUP(d, a)  asm("mov.b64 %0, {%1, %1};" : "=l"(d) : "f"(a))

// ---------------- scratch (device globals; no allocation) ----------------
__device__ float g_gates[TT * 48];
__device__ float g_kc[TT * 256];
__device__ float g_vc[TT * 256];
__device__ float g_ks[TT * 256];
__device__ float g_vs[TT * 256];
__device__ float g_kw[TT * 256];
__device__ float g_vw[TT * 256];
__device__ float g_ksum[NB * 256];
__device__ float g_vsum[NB * 256];
__device__ float g_outcmp[NQ * TT * DH];
__device__ float g_outslc[NQ * TT * DH];
__device__ int   g_sel[NKV * TT * TOPN];

// ================= fused GEMM: 6 projections + gates, f32x2, 8x8 microtile =================
__global__ __launch_bounds__(64) void gemm_all_kernel(
    const float* __restrict__ x,
    const float* __restrict__ gate_w, const float* __restrict__ gate_b,
    const float* __restrict__ wkc, const float* __restrict__ wvc,
    const float* __restrict__ wks, const float* __restrict__ wvs,
    const float* __restrict__ wkw, const float* __restrict__ wvw)
{
    __shared__ float As[16][64];
    __shared__ float Bs[16][64];

    const int b = blockIdx.x;
    const float* Bw;
    float* C;
    int Nn, ldc, m0, n0;
    bool gate = false;
    if (b < 384) {
        const int tz = b >> 6, rem = b & 63;
        switch (tz) {
            case 0: Bw = wkc; C = g_kc; break;
            case 1: Bw = wvc; C = g_vc; break;
            case 2: Bw = wks; C = g_ks; break;
            case 3: Bw = wvs; C = g_vs; break;
            case 4: Bw = wkw; C = g_kw; break;
            default: Bw = wvw; C = g_vw; break;
        }
        m0 = (rem >> 2) * 64; n0 = (rem & 3) * 64; Nn = 256; ldc = 256;
    } else {
        Bw = gate_w; C = g_gates;
        m0 = (b - 384) * 64; n0 = 0; Nn = 48; ldc = 48; gate = true;
    }

    const int tid = threadIdx.x;
    const int tx = tid & 7, ty = tid >> 3;
    const int lr = tid >> 2, lc4 = (tid & 3) << 2;

    ull acc[8][4];
#pragma unroll
    for (int i = 0; i < 8; i++)
#pragma unroll
        for (int j = 0; j < 4; j++) acc[i][j] = 0ull;

    for (int k0 = 0; k0 < DM; k0 += 16) {
#pragma unroll
        for (int p = 0; p < 4; p++) {
            const int row = lr + p * 16;
            float4 av = *(const float4*)(x + (m0 + row) * DM + k0 + lc4);
            As[lc4 + 0][row] = av.x; As[lc4 + 1][row] = av.y;
            As[lc4 + 2][row] = av.z; As[lc4 + 3][row] = av.w;
            float4 bv = make_float4(0.f, 0.f, 0.f, 0.f);
            const int n = n0 + row;
            if (n < Nn) bv = *(const float4*)(Bw + n * DM + k0 + lc4);
            Bs[lc4 + 0][row] = bv.x; Bs[lc4 + 1][row] = bv.y;
            Bs[lc4 + 2][row] = bv.z; Bs[lc4 + 3][row] = bv.w;
        }
        __syncthreads();
#pragma unroll
        for (int kk = 0; kk < 16; kk++) {
            float a8[8];
            *(float4*)(a8 + 0) = *(const float4*)&As[kk][ty * 8];
            *(float4*)(a8 + 4) = *(const float4*)&As[kk][ty * 8 + 4];
            ull b4[4];
#pragma unroll
            for (int j = 0; j < 4; j++) b4[j] = *(const ull*)&Bs[kk][tx * 8 + 2 * j];
#pragma unroll
            for (int i = 0; i < 8; i++) {
                ull aa; PACKDUP(aa, a8[i]);
#pragma unroll
                for (int j = 0; j < 4; j++) FMA2(acc[i][j], aa, b4[j]);
            }
        }
        __syncthreads();
    }

#pragma unroll
    for (int i = 0; i < 8; i++) {
        const int m = m0 + ty * 8 + i;
#pragma unroll
        for (int j = 0; j < 4; j++) {
            const int n = n0 + tx * 8 + 2 * j;
            if (n < Nn) {
                union { ull u; float2 f; } cv; cv.u = acc[i][j];
                float vx = cv.f.x, vy = cv.f.y;
                if (gate) {
                    vx += gate_b[n];     vy += gate_b[n + 1];
                    vx = 1.f / (1.f + expf(-vx));
                    vy = 1.f / (1.f + expf(-vy));
                }
                *(float2*)(C + m * ldc + n) = make_float2(vx, vy);
            }
        }
    }
}

// ================= block summaries: MLP(2048->64->64), k+v fused, kv-reuse =================
__global__ __launch_bounds__(512) void summarize_kernel(
    const float* __restrict__ bp,
    const float* __restrict__ ck1w, const float* __restrict__ ck1b,
    const float* __restrict__ ck2w, const float* __restrict__ ck2b,
    const float* __restrict__ cv1w, const float* __restrict__ cv1b,
    const float* __restrict__ cv2w, const float* __restrict__ cv2b)
{
    const int n = blockIdx.x, path = blockIdx.y;
    const float* src = path ? g_vc : g_kc;
    float* dst       = path ? g_vsum : g_ksum;
    const float* w1  = path ? cv1w : ck1w;
    const float* b1  = path ? cv1b : ck1b;
    const float* w2  = path ? cv2w : ck2w;
    const float* b2  = path ? cv2b : ck2b;

    __shared__ float flat[4][2048];
    __shared__ float hid[4][64];
    const int tid = threadIdx.x, warp = tid >> 5, lane = tid & 31;
    const int t0 = n * 16;

    for (int idx = tid; idx < 8192; idx += 512) {
        const int t = idx >> 8, c = idx & 255;
        flat[c >> 6][t * 64 + (c & 63)] = src[(t0 + t) * 256 + c] + bp[t * 64 + (c & 63)];
    }
    __syncthreads();

    float s[4][4];
#pragma unroll
    for (int oo = 0; oo < 4; oo++)
#pragma unroll
        for (int kv = 0; kv < 4; kv++) s[oo][kv] = 0.f;

    const float4* w1r0 = (const float4*)(w1 + (warp * 4 + 0) * 2048);
    const float4* w1r1 = (const float4*)(w1 + (warp * 4 + 1) * 2048);
    const float4* w1r2 = (const float4*)(w1 + (warp * 4 + 2) * 2048);
    const float4* w1r3 = (const float4*)(w1 + (warp * 4 + 3) * 2048);

#pragma unroll 4
    for (int c = 0; c < 16; c++) {
        const int off = lane + c * 32;
        float4 wv[4];
        wv[0] = w1r0[off]; wv[1] = w1r1[off]; wv[2] = w1r2[off]; wv[3] = w1r3[off];
#pragma unroll
        for (int kv = 0; kv < 4; kv++) {
            const float4 fv = ((const float4*)flat[kv])[off];
#pragma unroll
            for (int oo = 0; oo < 4; oo++)
                s[oo][kv] += wv[oo].x * fv.x + wv[oo].y * fv.y + wv[oo].z * fv.z + wv[oo].w * fv.w;
        }
    }
#pragma unroll
    for (int oo = 0; oo < 4; oo++)
#pragma unroll
        for (int kv = 0; kv < 4; kv++)
            for (int off = 16; off; off >>= 1)
                s[oo][kv] += __shfl_xor_sync(0xffffffffu, s[oo][kv], off);

    if (lane == 0) {
#pragma unroll
        for (int oo = 0; oo < 4; oo++) {
            const int o = warp * 4 + oo;
#pragma unroll
            for (int kv = 0; kv < 4; kv++) {
                float g = s[oo][kv] + b1[o];
                hid[kv][o] = 0.5f * g * (1.f + erff(g * 0.7071067811865476f));  // exact gelu
            }
        }
    }
    __syncthreads();

    if (tid < 256) {
        const int kv = tid >> 6, o = tid & 63;
        const float4* w2r = (const float4*)(w2 + o * 64);
        const float4* h4  = (const float4*)hid[kv];
        float s2 = b2[o];
#pragma unroll
        for (int c = 0; c < 16; c++) {
            float4 wv = w2r[c], hv = h4[c];
            s2 += wv.x * hv.x + wv.y * hv.y + wv.z * hv.z + wv.w * hv.w;
        }
        dst[n * 256 + kv * 64 + o] = s2;
    }
}

// ================= compressed attention + importance + warp-parallel top-8 =================
__global__ __launch_bounds__(128) void cmp_kernel(const float* __restrict__ q)
{
    const int t = blockIdx.x, kv = blockIdx.y;
    const int tid = threadIdx.x;            // 128 threads = 4 warps
    const int warp = tid >> 5, lane = tid & 31;
    __shared__ float4 qs4[4][16];
    __shared__ float4 ksT[16][65];          // [quad][block], pad 65 -> 2-way STS only
    __shared__ float p[4][64];
    __shared__ float impS[64];

    if (tid < 64) {
        int r = tid >> 4, c = tid & 15;
        qs4[r][c] = ((const float4*)(q + ((r * NKV + kv) * TT + t) * DH))[c];
    }
    // stage ksum transposed: idx -> (n = idx>>4, cq = idx&15); 16 consecutive lanes = one row
    for (int idx = tid; idx < NB * 16; idx += 128) {
        const int n = idx >> 4, cq = idx & 15;
        ksT[cq][n] = *(const float4*)(g_ksum + n * 256 + kv * 64 + cq * 4);
    }
    __syncthreads();

    const int nvis = (t >= 31) ? (((t - 31) >> 4) + 1) : 0;  // fully-past blocks

    const int n0 = lane, n1 = lane + 32;
    float d0 = -1e30f, d1 = -1e30f;
    {
        float a0 = 0.f, a1 = 0.f;
#pragma unroll
        for (int c = 0; c < 16; c++) {
            float4 qq = qs4[warp][c];
            float4 k0 = ksT[c][n0];
            a0 += qq.x * k0.x + qq.y * k0.y + qq.z * k0.z + qq.w * k0.w;
            if (n1 < NB) {
                float4 k1 = ksT[c][n1];
                a1 += qq.x * k1.x + qq.y * k1.y + qq.z * k1.z + qq.w * k1.w;
            }
        }
        if (n0 < nvis) d0 = a0 * SCALE;
        if (n1 < NB && n1 < nvis) d1 = a1 * SCALE;
    }
    if (nvis == 0) {
        p[warp][n0] = 1.f / 63.f;
        if (n1 < NB) p[warp][n1] = 1.f / 63.f;
    } else {
        float m = fmaxf(d0, d1);
        for (int o = 16; o; o >>= 1) m = fmaxf(m, __shfl_xor_sync(0xffffffffu, m, o));
        float e0 = (n0 < nvis) ? expf(d0 - m) : 0.f;
        float e1 = (n1 < NB && n1 < nvis) ? expf(d1 - m) : 0.f;
        float s = e0 + e1;
        for (int o = 16; o; o >>= 1) s += __shfl_xor_sync(0xffffffffu, s, o);
        float inv = 1.f / s;
        p[warp][n0] = e0 * inv;
        if (n1 < NB) p[warp][n1] = e1 * inv;
    }
    __syncthreads();

    if (tid < NB) impS[tid] = p[0][tid] + p[1][tid] + p[2][tid] + p[3][tid];

    for (int i = tid; i < 256; i += 128) {
        int r = i >> 6, d = i & 63;
        float a = 0.f;
        for (int nn = 0; nn < nvis; nn++) a += p[r][nn] * g_vsum[nn * 256 + kv * 64 + d];
        g_outcmp[((r * NKV + kv) * TT + t) * DH + d] = a;
    }
    __syncthreads();

    // warp-parallel top-8: argmax w/ lowest-index tie-break == serial strict-> scan
    if (warp == 0) {
        float v0 = (n0 < NB) ? impS[n0] : -2.f;
        float v1 = (n1 < NB) ? impS[n1] : -2.f;
#pragma unroll
        for (int it = 0; it < TOPN; it++) {
            float cv = v0; int ci = n0;
            if (v1 > cv) { cv = v1; ci = n1; }
            for (int off = 16; off; off >>= 1) {
                float ov = __shfl_xor_sync(0xffffffffu, cv, off);
                int   oi = __shfl_xor_sync(0xffffffffu, ci, off);
                if (ov > cv || (ov == cv && oi < ci)) { cv = ov; ci = oi; }
            }
            if (lane == 0) g_sel[(kv * TT + t) * TOPN + it] = ci;
            if (n0 == ci) v0 = -2.f;
            if (n1 == ci) v1 = -2.f;
        }
    }
}

// ================= 3-barrier softmax over sc rows (thread = position, 4 heads) ===============
__device__ __forceinline__ void softmax4_fast(float (&val)[4], float (&sc)[4][256],
                                              float (&redm)[4][8], float (&reds)[4][8],
                                              int tid, int warp, int lane)
{
#pragma unroll
    for (int r = 0; r < 4; r++) {
        float m = val[r];
        for (int o = 16; o; o >>= 1) m = fmaxf(m, __shfl_xor_sync(0xffffffffu, m, o));
        if (lane == 0) redm[r][warp] = m;
    }
    __syncthreads();
    float e[4];
#pragma unroll
    for (int r = 0; r < 4; r++) {
        float m = redm[r][0];
#pragma unroll
        for (int w = 1; w < 8; w++) m = fmaxf(m, redm[r][w]);
        e[r] = expf(val[r] - m);
        float s = e[r];
        for (int o = 16; o; o >>= 1) s += __shfl_xor_sync(0xffffffffu, s, o);
        if (lane == 0) reds[r][warp] = s;
    }
    __syncthreads();
#pragma unroll
    for (int r = 0; r < 4; r++) {
        float s = reds[r][0];
#pragma unroll
        for (int w = 1; w < 8; w++) s += reds[r][w];
        sc[r][tid] = e[r] / s;
    }
    __syncthreads();
}

// Ks chunk buffer (33KB) unioned with the AV partial buffer (17.4KB): disjoint lifetimes.
#define KS_STRIDE 129

// ================= selected-blocks attention =================
__global__ __launch_bounds__(256) void slc_kernel(const float* __restrict__ q)
{
    const int t = blockIdx.x, kv = blockIdx.y, tid = threadIdx.x;
    const int warp = tid >> 5, lane = tid & 31;
    __shared__ float4 qs4[4][16];
    __shared__ float sc[4][256];
    __shared__ int   pos[256];
    __shared__ float redm[4][8], reds[4][8];
    __shared__ float4 shbuf[16 * KS_STRIDE];          // Ks[quad][p] | part[4][16][17]
    float4* Ks = shbuf;
    float4 (*part)[16][17] = (float4(*)[16][17])shbuf;

    if (tid < 64) {
        int r = tid >> 4, c = tid & 15;
        qs4[r][c] = ((const float4*)(q + ((r * NKV + kv) * TT + t) * DH))[c];
    }
    {
        int blk = g_sel[(kv * TT + t) * TOPN + (tid >> 5)];
        pos[tid] = blk * 16 + (tid & 31);    // starts[blk] + offset, always < T
    }
    __syncthreads();

    const int sub = tid >> 4, dq = tid & 15;
    const int p0 = tid & 127, hp = tid >> 7;

#pragma unroll
    for (int c = 0; c < 2; c++) {
        // stage 128 positions, transposed: coalesced LDG (16 lanes = one row's 256B)
#pragma unroll
        for (int i = 0; i < 8; i++) {
            const int pp = sub * 8 + i;
            const int ps = pos[c * 128 + pp];
            Ks[dq * KS_STRIDE + pp] = *(const float4*)(g_ks + ps * 256 + kv * 64 + dq * 4);
        }
        __syncthreads();
        // scores: thread-per-position (conflict-free LDS), 2 heads per thread
        {
            const int s2 = c * 128 + p0;
            const bool valid = (pos[s2] <= t);
            float a0 = 0.f, a1 = 0.f;
#pragma unroll
            for (int cq = 0; cq < 16; cq++) {
                const float4 kk = Ks[cq * KS_STRIDE + p0];
                const float4 q0 = qs4[2 * hp][cq], q1 = qs4[2 * hp + 1][cq];
                a0 += q0.x * kk.x + q0.y * kk.y + q0.z * kk.z + q0.w * kk.w;
                a1 += q1.x * kk.x + q1.y * kk.y + q1.z * kk.z + q1.w * kk.w;
            }
            sc[2 * hp][s2]     = valid ? a0 * SCALE : -1e30f;
            sc[2 * hp + 1][s2] = valid ? a1 * SCALE : -1e30f;
        }
        __syncthreads();
    }

    float val[4];
#pragma unroll
    for (int r = 0; r < 4; r++) val[r] = sc[r][tid];
    softmax4_fast(val, sc, redm, reds, tid, warp, lane);

    // AV: V loaded once (coalesced), shared by 4 heads; partials reduced via smem
    float4 a0 = make_float4(0,0,0,0), a1 = a0, a2 = a0, a3 = a0;
#pragma unroll 4
    for (int i = 0; i < 16; i++) {
        const int s2 = sub * 16 + i;
        const float4 vv = *(const float4*)(g_vs + pos[s2] * 256 + kv * 64 + dq * 4);
        float pp0 = sc[0][s2], pp1 = sc[1][s2], pp2 = sc[2][s2], pp3 = sc[3][s2];
        a0.x += pp0 * vv.x; a0.y += pp0 * vv.y; a0.z += pp0 * vv.z; a0.w += pp0 * vv.w;
        a1.x += pp1 * vv.x; a1.y += pp1 * vv.y; a1.z += pp1 * vv.z; a1.w += pp1 * vv.w;
        a2.x += pp2 * vv.x; a2.y += pp2 * vv.y; a2.z += pp2 * vv.z; a2.w += pp2 * vv.w;
        a3.x += pp3 * vv.x; a3.y += pp3 * vv.y; a3.z += pp3 * vv.z; a3.w += pp3 * vv.w;
    }
    __syncthreads();                       // Ks lifetime over before part writes
    part[0][sub][dq] = a0; part[1][sub][dq] = a1;
    part[2][sub][dq] = a2; part[3][sub][dq] = a3;
    __syncthreads();
    if (tid < 64) {
        const int r = tid >> 4, dq2 = tid & 15;
        float4 s = make_float4(0,0,0,0);
#pragma unroll
        for (int u = 0; u < 16; u++) {
            float4 pv = part[r][u][dq2];
            s.x += pv.x; s.y += pv.y; s.z += pv.z; s.w += pv.w;
        }
        ((float4*)(g_outslc + ((r * NKV + kv) * TT + t) * DH))[dq2] = s;
    }
}

// ================= sliding window attention + gating + final output =================
__global__ __launch_bounds__(256) void win_final_kernel(const float* __restrict__ q,
                                                        float* __restrict__ out)
{
    const int t = blockIdx.x, kv = blockIdx.y, tid = threadIdx.x;
    const int warp = tid >> 5, lane = tid & 31;
    __shared__ float4 qs4[4][16];
    __shared__ float sc[4][256];
    __shared__ float redm[4][8], reds[4][8];
    __shared__ float4 shbuf[16 * KS_STRIDE];
    float4* Ks = shbuf;
    float4 (*part)[16][17] = (float4(*)[16][17])shbuf;

    const int j0 = (t >= WIN - 1) ? t - (WIN - 1) : 0;
    const int nj = t - j0 + 1;

    if (tid < 64) {
        int r = tid >> 4, c = tid & 15;
        qs4[r][c] = ((const float4*)(q + ((r * NKV + kv) * TT + t) * DH))[c];
    }
    __syncthreads();

    const int sub = tid >> 4, dq = tid & 15;
    const int p0 = tid & 127, hp = tid >> 7;

#pragma unroll
    for (int c = 0; c < 2; c++) {
#pragma unroll
        for (int i = 0; i < 8; i++) {
            const int pp = sub * 8 + i;
            const int row = j0 + c * 128 + pp;   // always < TT
            Ks[dq * KS_STRIDE + pp] = *(const float4*)(g_kw + row * 256 + kv * 64 + dq * 4);
        }
        __syncthreads();
        {
            const int s2 = c * 128 + p0;
            const bool valid = (s2 < nj);
            float a0 = 0.f, a1 = 0.f;
#pragma unroll
            for (int cq = 0; cq < 16; cq++) {
                const float4 kk = Ks[cq * KS_STRIDE + p0];
                const float4 q0 = qs4[2 * hp][cq], q1 = qs4[2 * hp + 1][cq];
                a0 += q0.x * kk.x + q0.y * kk.y + q0.z * kk.z + q0.w * kk.w;
                a1 += q1.x * kk.x + q1.y * kk.y + q1.z * kk.z + q1.w * kk.w;
            }
            sc[2 * hp][s2]     = valid ? a0 * SCALE : -1e30f;
            sc[2 * hp + 1][s2] = valid ? a1 * SCALE : -1e30f;
        }
        __syncthreads();
    }

    float val[4];
#pragma unroll
    for (int r = 0; r < 4; r++) val[r] = sc[r][tid];
    softmax4_fast(val, sc, redm, reds, tid, warp, lane);

    float4 a0 = make_float4(0,0,0,0), a1 = a0, a2 = a0, a3 = a0;
#pragma unroll 4
    for (int i = 0; i < 16; i++) {
        const int s2 = sub * 16 + i;
        const float4 vv = *(const float4*)(g_vw + (j0 + s2) * 256 + kv * 64 + dq * 4);
        float pp0 = sc[0][s2], pp1 = sc[1][s2], pp2 = sc[2][s2], pp3 = sc[3][s2];
        a0.x += pp0 * vv.x; a0.y += pp0 * vv.y; a0.z += pp0 * vv.z; a0.w += pp0 * vv.w;
        a1.x += pp1 * vv.x; a1.y += pp1 * vv.y; a1.z += pp1 * vv.z; a1.w += pp1 * vv.w;
        a2.x += pp2 * vv.x; a2.y += pp2 * vv.y; a2.z += pp2 * vv.z; a2.w += pp2 * vv.w;
        a3.x += pp3 * vv.x; a3.y += pp3 * vv.y; a3.z += pp3 * vv.z; a3.w += pp3 * vv.w;
    }
    __syncthreads();
    part[0][sub][dq] = a0; part[1][sub][dq] = a1;
    part[2][sub][dq] = a2; part[3][sub][dq] = a3;
    __syncthreads();
    if (tid < 64) {
        const int r = tid >> 4, dq2 = tid & 15;
        float4 s = make_float4(0,0,0,0);
#pragma unroll
        for (int u = 0; u < 16; u++) {
            float4 pv = part[r][u][dq2];
            s.x += pv.x; s.y += pv.y; s.z += pv.z; s.w += pv.w;
        }
        const int h = r * NKV + kv;
        const float g0 = g_gates[t * 48 + h * 3 + 0];
        const float g1 = g_gates[t * 48 + h * 3 + 1];
        const float g2 = g_gates[t * 48 + h * 3 + 2];
        const int obase = (h * TT + t) * DH;
        float4 oc = ((const float4*)(g_outcmp + obase))[dq2];
        float4 os = ((const float4*)(g_outslc + obase))[dq2];
        float4 res;
        res.x = g0 * oc.x + g1 * os.x + g2 * s.x;
        res.y = g0 * oc.y + g1 * os.y + g2 * s.y;
        res.z = g0 * oc.z + g1 * os.z + g2 * s.z;
        res.w = g0 * oc.w + g1 * os.w + g2 * s.w;
        ((float4*)(out + obase))[dq2] = res;
    }
}

// ---------------- launch ----------------
extern "C" void kernel_launch(void* const* d_in, const int* in_sizes, int n_in,
                              void* d_out, int out_size)
{
    (void)in_sizes; (void)n_in; (void)out_size;
    const float* x       = (const float*)d_in[0];
    const float* q       = (const float*)d_in[1];
    const float* gate_w  = (const float*)d_in[2];
    const float* gate_b  = (const float*)d_in[3];
    const float* wk_cmp  = (const float*)d_in[4];
    const float* wv_cmp  = (const float*)d_in[5];
    const float* wk_slc  = (const float*)d_in[6];
    const float* wv_slc  = (const float*)d_in[7];
    const float* wk_win  = (const float*)d_in[8];
    const float* wv_win  = (const float*)d_in[9];
    const float* blockp  = (const float*)d_in[10];
    const float* ck1_w   = (const float*)d_in[11];
    const float* ck1_b   = (const float*)d_in[12];
    const float* ck2_w   = (const float*)d_in[13];
    const float* ck2_b   = (const float*)d_in[14];
    const float* cv1_w   = (const float*)d_in[15];
    const float* cv1_b   = (const float*)d_in[16];
    const float* cv2_w   = (const float*)d_in[17];
    const float* cv2_b   = (const float*)d_in[18];
    float* out = (float*)d_out;

    gemm_all_kernel<<<400, 64>>>(x, gate_w, gate_b,
                                 wk_cmp, wv_cmp, wk_slc, wv_slc, wk_win, wv_win);
    summarize_kernel<<<dim3(NB, 2), 512>>>(blockp,
                                           ck1_w, ck1_b, ck2_w, ck2_b,
                                           cv1_w, cv1_b, cv2_w, cv2_b);
    cmp_kernel<<<dim3(TT, NKV), 128>>>(q);
    slc_kernel<<<dim3(TT, NKV), 256>>>(q);
    win_final_kernel<<<dim3(TT, NKV), 256>>>(q, out);
}

// round 11
// speedup vs baseline: 1.1921x; 1.1921x over previous
#include <cuda_runtime.h>
#include <math.h>

#define TT   1024
#define DM   1024
#define NQ   16
#define NKV  4
#define DH   64
#define NB   63
#define TOPN 8
#define WIN  256
#define SCALE 0.125f

typedef unsigned long long ull;

// packed fp32x2 FMA: d = a*b + d  (per 32-bit half) -> SASS FFMA2
#define FMA2(d, a, b)  asm("fma.rn.f32x2 %0, %1, %2, %0;" : "+l"(d) : "l"(a), "l"(b))
// duplicate one float into both halves of a b64
#define PACKDUP(d, a)  asm("mov.b64 %0, {%1, %1};" : "=l"(d) : "f"(a))

// ---------------- scratch (device globals; no allocation) ----------------
__device__ float g_gates[TT * 48];
__device__ float g_kc[TT * 256];
__device__ float g_vc[TT * 256];
__device__ float g_vs[TT * 256];
__device__ float g_vw[TT * 256];
// K tensors stored quad-transposed: KT[kv][quad][pos] as float4 = dims 4q..4q+3 of pos
__device__ float4 g_ksT[NKV * 16 * TT];
__device__ float4 g_kwT[NKV * 16 * TT];
__device__ float4 g_ksumT[NKV * 16 * 64];   // [kv][quad][block], padded to 64 blocks
__device__ float g_vsum[NB * 256];
__device__ float g_outcmp[NQ * TT * DH];
__device__ float g_outslc[NQ * TT * DH];
__device__ int   g_sel[NKV * TT * TOPN];

// ================= fused GEMM: 6 projections + gates, f32x2, 8x8 microtile =================
// tz 2 (k_slc) and 4 (k_win) write quad-transposed layout; others row-major.
__global__ __launch_bounds__(64) void gemm_all_kernel(
    const float* __restrict__ x,
    const float* __restrict__ gate_w, const float* __restrict__ gate_b,
    const float* __restrict__ wkc, const float* __restrict__ wvc,
    const float* __restrict__ wks, const float* __restrict__ wvs,
    const float* __restrict__ wkw, const float* __restrict__ wvw)
{
    __shared__ float As[16][64];
    __shared__ float Bs[16][64];

    const int b = blockIdx.x;
    const float* Bw;
    float* C = 0;
    float* KT = 0;
    int Nn, ldc = 256, m0, n0;
    bool gate = false;
    if (b < 384) {
        const int tz = b >> 6, rem = b & 63;
        switch (tz) {
            case 0: Bw = wkc; C = g_kc; break;
            case 1: Bw = wvc; C = g_vc; break;
            case 2: Bw = wks; KT = (float*)g_ksT; break;
            case 3: Bw = wvs; C = g_vs; break;
            case 4: Bw = wkw; KT = (float*)g_kwT; break;
            default: Bw = wvw; C = g_vw; break;
        }
        m0 = (rem >> 2) * 64; n0 = (rem & 3) * 64; Nn = 256;
    } else {
        Bw = gate_w; C = g_gates;
        m0 = (b - 384) * 64; n0 = 0; Nn = 48; ldc = 48; gate = true;
    }

    const int tid = threadIdx.x;
    const int tx = tid & 7, ty = tid >> 3;
    const int lr = tid >> 2, lc4 = (tid & 3) << 2;

    ull acc[8][4];
#pragma unroll
    for (int i = 0; i < 8; i++)
#pragma unroll
        for (int j = 0; j < 4; j++) acc[i][j] = 0ull;

    for (int k0 = 0; k0 < DM; k0 += 16) {
#pragma unroll
        for (int p = 0; p < 4; p++) {
            const int row = lr + p * 16;
            float4 av = *(const float4*)(x + (m0 + row) * DM + k0 + lc4);
            As[lc4 + 0][row] = av.x; As[lc4 + 1][row] = av.y;
            As[lc4 + 2][row] = av.z; As[lc4 + 3][row] = av.w;
            float4 bv = make_float4(0.f, 0.f, 0.f, 0.f);
            const int n = n0 + row;
            if (n < Nn) bv = *(const float4*)(Bw + n * DM + k0 + lc4);
            Bs[lc4 + 0][row] = bv.x; Bs[lc4 + 1][row] = bv.y;
            Bs[lc4 + 2][row] = bv.z; Bs[lc4 + 3][row] = bv.w;
        }
        __syncthreads();
#pragma unroll
        for (int kk = 0; kk < 16; kk++) {
            float a8[8];
            *(float4*)(a8 + 0) = *(const float4*)&As[kk][ty * 8];
            *(float4*)(a8 + 4) = *(const float4*)&As[kk][ty * 8 + 4];
            ull b4[4];
#pragma unroll
            for (int j = 0; j < 4; j++) b4[j] = *(const ull*)&Bs[kk][tx * 8 + 2 * j];
#pragma unroll
            for (int i = 0; i < 8; i++) {
                ull aa; PACKDUP(aa, a8[i]);
#pragma unroll
                for (int j = 0; j < 4; j++) FMA2(acc[i][j], aa, b4[j]);
            }
        }
        __syncthreads();
    }

#pragma unroll
    for (int i = 0; i < 8; i++) {
        const int m = m0 + ty * 8 + i;
#pragma unroll
        for (int j = 0; j < 4; j++) {
            const int n = n0 + tx * 8 + 2 * j;
            if (n >= Nn) continue;
            union { ull u; float2 f; } cv; cv.u = acc[i][j];
            float vx = cv.f.x, vy = cv.f.y;
            if (KT) {
                // quad-transposed: KT[((kv*16+q)*1024 + m)*4 + c], c in {0,2}
                const int kv = n >> 6, d = n & 63;
                *(float2*)(KT + (((kv * 16 + (d >> 2)) * 1024 + m) << 2) + (d & 3))
                    = make_float2(vx, vy);
            } else {
                if (gate) {
                    vx += gate_b[n];     vy += gate_b[n + 1];
                    vx = 1.f / (1.f + expf(-vx));
                    vy = 1.f / (1.f + expf(-vy));
                }
                *(float2*)(C + m * ldc + n) = make_float2(vx, vy);
            }
        }
    }
}

// ================= block summaries: MLP(2048->64->64), k+v fused, kv-reuse =================
// k-path (path==0) reads g_kc, writes transposed g_ksumT; v-path writes row-major g_vsum.
__global__ __launch_bounds__(512) void summarize_kernel(
    const float* __restrict__ bp,
    const float* __restrict__ ck1w, const float* __restrict__ ck1b,
    const float* __restrict__ ck2w, const float* __restrict__ ck2b,
    const float* __restrict__ cv1w, const float* __restrict__ cv1b,
    const float* __restrict__ cv2w, const float* __restrict__ cv2b)
{
    const int n = blockIdx.x, path = blockIdx.y;
    const float* src = path ? g_vc : g_kc;
    const float* w1  = path ? cv1w : ck1w;
    const float* b1  = path ? cv1b : ck1b;
    const float* w2  = path ? cv2w : ck2w;
    const float* b2  = path ? cv2b : ck2b;

    __shared__ float flat[4][2048];
    __shared__ float hid[4][64];
    const int tid = threadIdx.x, warp = tid >> 5, lane = tid & 31;
    const int t0 = n * 16;

    for (int idx = tid; idx < 8192; idx += 512) {
        const int t = idx >> 8, c = idx & 255;
        flat[c >> 6][t * 64 + (c & 63)] = src[(t0 + t) * 256 + c] + bp[t * 64 + (c & 63)];
    }
    __syncthreads();

    float s[4][4];
#pragma unroll
    for (int oo = 0; oo < 4; oo++)
#pragma unroll
        for (int kv = 0; kv < 4; kv++) s[oo][kv] = 0.f;

    const float4* w1r0 = (const float4*)(w1 + (warp * 4 + 0) * 2048);
    const float4* w1r1 = (const float4*)(w1 + (warp * 4 + 1) * 2048);
    const float4* w1r2 = (const float4*)(w1 + (warp * 4 + 2) * 2048);
    const float4* w1r3 = (const float4*)(w1 + (warp * 4 + 3) * 2048);

#pragma unroll 4
    for (int c = 0; c < 16; c++) {
        const int off = lane + c * 32;
        float4 wv[4];
        wv[0] = w1r0[off]; wv[1] = w1r1[off]; wv[2] = w1r2[off]; wv[3] = w1r3[off];
#pragma unroll
        for (int kv = 0; kv < 4; kv++) {
            const float4 fv = ((const float4*)flat[kv])[off];
#pragma unroll
            for (int oo = 0; oo < 4; oo++)
                s[oo][kv] += wv[oo].x * fv.x + wv[oo].y * fv.y + wv[oo].z * fv.z + wv[oo].w * fv.w;
        }
    }
#pragma unroll
    for (int oo = 0; oo < 4; oo++)
#pragma unroll
        for (int kv = 0; kv < 4; kv++)
            for (int off = 16; off; off >>= 1)
                s[oo][kv] += __shfl_xor_sync(0xffffffffu, s[oo][kv], off);

    if (lane == 0) {
#pragma unroll
        for (int oo = 0; oo < 4; oo++) {
            const int o = warp * 4 + oo;
#pragma unroll
            for (int kv = 0; kv < 4; kv++) {
                float g = s[oo][kv] + b1[o];
                hid[kv][o] = 0.5f * g * (1.f + erff(g * 0.7071067811865476f));  // exact gelu
            }
        }
    }
    __syncthreads();

    if (tid < 256) {
        const int kv = tid >> 6, o = tid & 63;
        const float4* w2r = (const float4*)(w2 + o * 64);
        const float4* h4  = (const float4*)hid[kv];
        float s2 = b2[o];
#pragma unroll
        for (int c = 0; c < 16; c++) {
            float4 wv = w2r[c], hv = h4[c];
            s2 += wv.x * hv.x + wv.y * hv.y + wv.z * hv.z + wv.w * hv.w;
        }
        if (path)
            g_vsum[n * 256 + kv * 64 + o] = s2;
        else
            ((float*)g_ksumT)[(((kv * 16 + (o >> 2)) * 64 + n) << 2) + (o & 3)] = s2;
    }
}

// ================= compressed attention + importance + warp-parallel top-8 =================
__global__ __launch_bounds__(128) void cmp_kernel(const float* __restrict__ q)
{
    const int t = blockIdx.x, kv = blockIdx.y;
    const int tid = threadIdx.x;            // 128 threads = 4 warps
    const int warp = tid >> 5, lane = tid & 31;
    __shared__ float4 qs4[4][16];
    __shared__ float p[4][64];
    __shared__ float impS[64];

    if (tid < 64) {
        int r = tid >> 4, c = tid & 15;
        qs4[r][c] = ((const float4*)(q + ((r * NKV + kv) * TT + t) * DH))[c];
    }
    __syncthreads();

    const int nvis = (t >= 31) ? (((t - 31) >> 4) + 1) : 0;  // fully-past blocks

    const int n0 = lane, n1 = lane + 32;
    float d0 = -1e30f, d1 = -1e30f;
    {
        float a0 = 0.f, a1 = 0.f;
#pragma unroll
        for (int c = 0; c < 16; c++) {
            float4 qq = qs4[warp][c];
            float4 k0 = g_ksumT[(kv * 16 + c) * 64 + n0];     // lanes consecutive -> coalesced
            a0 += qq.x * k0.x + qq.y * k0.y + qq.z * k0.z + qq.w * k0.w;
            if (n1 < NB) {
                float4 k1 = g_ksumT[(kv * 16 + c) * 64 + n1];
                a1 += qq.x * k1.x + qq.y * k1.y + qq.z * k1.z + qq.w * k1.w;
            }
        }
        if (n0 < nvis) d0 = a0 * SCALE;
        if (n1 < NB && n1 < nvis) d1 = a1 * SCALE;
    }
    if (nvis == 0) {
        p[warp][n0] = 1.f / 63.f;
        if (n1 < NB) p[warp][n1] = 1.f / 63.f;
    } else {
        float m = fmaxf(d0, d1);
        for (int o = 16; o; o >>= 1) m = fmaxf(m, __shfl_xor_sync(0xffffffffu, m, o));
        float e0 = (n0 < nvis) ? expf(d0 - m) : 0.f;
        float e1 = (n1 < NB && n1 < nvis) ? expf(d1 - m) : 0.f;
        float s = e0 + e1;
        for (int o = 16; o; o >>= 1) s += __shfl_xor_sync(0xffffffffu, s, o);
        float inv = 1.f / s;
        p[warp][n0] = e0 * inv;
        if (n1 < NB) p[warp][n1] = e1 * inv;
    }
    __syncthreads();

    if (tid < NB) impS[tid] = p[0][tid] + p[1][tid] + p[2][tid] + p[3][tid];

    for (int i = tid; i < 256; i += 128) {
        int r = i >> 6, d = i & 63;
        float a = 0.f;
        for (int nn = 0; nn < nvis; nn++) a += p[r][nn] * g_vsum[nn * 256 + kv * 64 + d];
        g_outcmp[((r * NKV + kv) * TT + t) * DH + d] = a;
    }
    __syncthreads();

    // warp-parallel top-8: argmax w/ lowest-index tie-break == serial strict-> scan
    if (warp == 0) {
        float v0 = (n0 < NB) ? impS[n0] : -2.f;
        float v1 = (n1 < NB) ? impS[n1] : -2.f;
#pragma unroll
        for (int it = 0; it < TOPN; it++) {
            float cv = v0; int ci = n0;
            if (v1 > cv) { cv = v1; ci = n1; }
            for (int off = 16; off; off >>= 1) {
                float ov = __shfl_xor_sync(0xffffffffu, cv, off);
                int   oi = __shfl_xor_sync(0xffffffffu, ci, off);
                if (ov > cv || (ov == cv && oi < ci)) { cv = ov; ci = oi; }
            }
            if (lane == 0) g_sel[(kv * TT + t) * TOPN + it] = ci;
            if (n0 == ci) v0 = -2.f;
            if (n1 == ci) v1 = -2.f;
        }
    }
}

// ================= 3-barrier softmax over sc rows (thread = position, 4 heads) ===============
__device__ __forceinline__ void softmax4_fast(float (&val)[4], float (&sc)[4][256],
                                              float (&redm)[4][8], float (&reds)[4][8],
                                              int tid, int warp, int lane)
{
#pragma unroll
    for (int r = 0; r < 4; r++) {
        float m = val[r];
        for (int o = 16; o; o >>= 1) m = fmaxf(m, __shfl_xor_sync(0xffffffffu, m, o));
        if (lane == 0) redm[r][warp] = m;
    }
    __syncthreads();
    float e[4];
#pragma unroll
    for (int r = 0; r < 4; r++) {
        float m = redm[r][0];
#pragma unroll
        for (int w = 1; w < 8; w++) m = fmaxf(m, redm[r][w]);
        e[r] = expf(val[r] - m);
        float s = e[r];
        for (int o = 16; o; o >>= 1) s += __shfl_xor_sync(0xffffffffu, s, o);
        if (lane == 0) reds[r][warp] = s;
    }
    __syncthreads();
#pragma unroll
    for (int r = 0; r < 4; r++) {
        float s = reds[r][0];
#pragma unroll
        for (int w = 1; w < 8; w++) s += reds[r][w];
        sc[r][tid] = e[r] / s;
    }
    __syncthreads();
}

// ================= selected-blocks attention =================
__global__ __launch_bounds__(256) void slc_kernel(const float* __restrict__ q)
{
    const int t = blockIdx.x, kv = blockIdx.y, tid = threadIdx.x;
    const int warp = tid >> 5, lane = tid & 31;
    __shared__ float4 qs4[4][16];
    __shared__ float sc[4][256];
    __shared__ int   pos[256];
    __shared__ float redm[4][8], reds[4][8];
    __shared__ float4 part[4][16][17];

    if (tid < 64) {
        int r = tid >> 4, c = tid & 15;
        qs4[r][c] = ((const float4*)(q + ((r * NKV + kv) * TT + t) * DH))[c];
    }
    {
        int blk = g_sel[(kv * TT + t) * TOPN + (tid >> 5)];
        pos[tid] = blk * 16 + (tid & 31);    // starts[blk] + offset, always < T; warp-contiguous
    }
    __syncthreads();

    const int ps = pos[tid];
    const bool valid = (ps <= t);
    float val[4];
    if (valid) {
        float acc[4] = {0.f, 0.f, 0.f, 0.f};
        const float4* kt = g_ksT + kv * 16 * TT + ps;
#pragma unroll
        for (int c = 0; c < 16; c++) {
            float4 kk = kt[c * TT];          // lanes = consecutive ps -> coalesced 512B
#pragma unroll
            for (int r = 0; r < 4; r++) {
                float4 qq = qs4[r][c];
                acc[r] += qq.x * kk.x + qq.y * kk.y + qq.z * kk.z + qq.w * kk.w;
            }
        }
#pragma unroll
        for (int r = 0; r < 4; r++) val[r] = acc[r] * SCALE;
    } else {
#pragma unroll
        for (int r = 0; r < 4; r++) val[r] = -1e30f;
    }

    softmax4_fast(val, sc, redm, reds, tid, warp, lane);

    // AV: V row-major, (sub,dq) mapping -> coalesced; V loaded once, shared by 4 heads
    const int sub = tid >> 4, dq = tid & 15;
    float4 a0 = make_float4(0,0,0,0), a1 = a0, a2 = a0, a3 = a0;
#pragma unroll 4
    for (int i = 0; i < 16; i++) {
        const int s2 = sub * 16 + i;
        const float4 vv = *(const float4*)(g_vs + pos[s2] * 256 + kv * 64 + dq * 4);
        float pp0 = sc[0][s2], pp1 = sc[1][s2], pp2 = sc[2][s2], pp3 = sc[3][s2];
        a0.x += pp0 * vv.x; a0.y += pp0 * vv.y; a0.z += pp0 * vv.z; a0.w += pp0 * vv.w;
        a1.x += pp1 * vv.x; a1.y += pp1 * vv.y; a1.z += pp1 * vv.z; a1.w += pp1 * vv.w;
        a2.x += pp2 * vv.x; a2.y += pp2 * vv.y; a2.z += pp2 * vv.z; a2.w += pp2 * vv.w;
        a3.x += pp3 * vv.x; a3.y += pp3 * vv.y; a3.z += pp3 * vv.z; a3.w += pp3 * vv.w;
    }
    part[0][sub][dq] = a0; part[1][sub][dq] = a1;
    part[2][sub][dq] = a2; part[3][sub][dq] = a3;
    __syncthreads();
    if (tid < 64) {
        const int r = tid >> 4, dq2 = tid & 15;
        float4 s = make_float4(0,0,0,0);
#pragma unroll
        for (int u = 0; u < 16; u++) {
            float4 pv = part[r][u][dq2];
            s.x += pv.x; s.y += pv.y; s.z += pv.z; s.w += pv.w;
        }
        ((float4*)(g_outslc + ((r * NKV + kv) * TT + t) * DH))[dq2] = s;
    }
}

// ================= sliding window attention + gating + final output =================
__global__ __launch_bounds__(256) void win_final_kernel(const float* __restrict__ q,
                                                        float* __restrict__ out)
{
    const int t = blockIdx.x, kv = blockIdx.y, tid = threadIdx.x;
    const int warp = tid >> 5, lane = tid & 31;
    __shared__ float4 qs4[4][16];
    __shared__ float sc[4][256];
    __shared__ float redm[4][8], reds[4][8];
    __shared__ float4 part[4][16][17];

    const int j0 = (t >= WIN - 1) ? t - (WIN - 1) : 0;
    const int nj = t - j0 + 1;

    if (tid < 64) {
        int r = tid >> 4, c = tid & 15;
        qs4[r][c] = ((const float4*)(q + ((r * NKV + kv) * TT + t) * DH))[c];
    }
    __syncthreads();

    const bool valid = (tid < nj);
    float val[4];
    if (valid) {
        float acc[4] = {0.f, 0.f, 0.f, 0.f};
        const float4* kt = g_kwT + kv * 16 * TT + (j0 + tid);
#pragma unroll
        for (int c = 0; c < 16; c++) {
            float4 kk = kt[c * TT];          // lanes consecutive -> coalesced
#pragma unroll
            for (int r = 0; r < 4; r++) {
                float4 qq = qs4[r][c];
                acc[r] += qq.x * kk.x + qq.y * kk.y + qq.z * kk.z + qq.w * kk.w;
            }
        }
#pragma unroll
        for (int r = 0; r < 4; r++) val[r] = acc[r] * SCALE;
    } else {
#pragma unroll
        for (int r = 0; r < 4; r++) val[r] = -1e30f;
    }

    softmax4_fast(val, sc, redm, reds, tid, warp, lane);

    const int sub = tid >> 4, dq = tid & 15;
    float4 a0 = make_float4(0,0,0,0), a1 = a0, a2 = a0, a3 = a0;
#pragma unroll 4
    for (int i = 0; i < 16; i++) {
        const int s2 = sub * 16 + i;
        const float4 vv = *(const float4*)(g_vw + (j0 + s2) * 256 + kv * 64 + dq * 4);
        float pp0 = sc[0][s2], pp1 = sc[1][s2], pp2 = sc[2][s2], pp3 = sc[3][s2];
        a0.x += pp0 * vv.x; a0.y += pp0 * vv.y; a0.z += pp0 * vv.z; a0.w += pp0 * vv.w;
        a1.x += pp1 * vv.x; a1.y += pp1 * vv.y; a1.z += pp1 * vv.z; a1.w += pp1 * vv.w;
        a2.x += pp2 * vv.x; a2.y += pp2 * vv.y; a2.z += pp2 * vv.z; a2.w += pp2 * vv.w;
        a3.x += pp3 * vv.x; a3.y += pp3 * vv.y; a3.z += pp3 * vv.z; a3.w += pp3 * vv.w;
    }
    part[0][sub][dq] = a0; part[1][sub][dq] = a1;
    part[2][sub][dq] = a2; part[3][sub][dq] = a3;
    __syncthreads();
    if (tid < 64) {
        const int r = tid >> 4, dq2 = tid & 15;
        float4 s = make_float4(0,0,0,0);
#pragma unroll
        for (int u = 0; u < 16; u++) {
            float4 pv = part[r][u][dq2];
            s.x += pv.x; s.y += pv.y; s.z += pv.z; s.w += pv.w;
        }
        const int h = r * NKV + kv;
        const float g0 = g_gates[t * 48 + h * 3 + 0];
        const float g1 = g_gates[t * 48 + h * 3 + 1];
        const float g2 = g_gates[t * 48 + h * 3 + 2];
        const int obase = (h * TT + t) * DH;
        float4 oc = ((const float4*)(g_outcmp + obase))[dq2];
        float4 os = ((const float4*)(g_outslc + obase))[dq2];
        float4 res;
        res.x = g0 * oc.x + g1 * os.x + g2 * s.x;
        res.y = g0 * oc.y + g1 * os.y + g2 * s.y;
        res.z = g0 * oc.z + g1 * os.z + g2 * s.z;
        res.w = g0 * oc.w + g1 * os.w + g2 * s.w;
        ((float4*)(out + obase))[dq2] = res;
    }
}

// ---------------- launch ----------------
extern "C" void kernel_launch(void* const* d_in, const int* in_sizes, int n_in,
                              void* d_out, int out_size)
{
    (void)in_sizes; (void)n_in; (void)out_size;
    const float* x       = (const float*)d_in[0];
    const float* q       = (const float*)d_in[1];
    const float* gate_w  = (const float*)d_in[2];
    const float* gate_b  = (const float*)d_in[3];
    const float* wk_cmp  = (const float*)d_in[4];
    const float* wv_cmp  = (const float*)d_in[5];
    const float* wk_slc  = (const float*)d_in[6];
    const float* wv_slc  = (const float*)d_in[7];
    const float* wk_win  = (const float*)d_in[8];
    const float* wv_win  = (const float*)d_in[9];
    const float* blockp  = (const float*)d_in[10];
    const float* ck1_w   = (const float*)d_in[11];
    const float* ck1_b   = (const float*)d_in[12];
    const float* ck2_w   = (const float*)d_in[13];
    const float* ck2_b   = (const float*)d_in[14];
    const float* cv1_w   = (const float*)d_in[15];
    const float* cv1_b   = (const float*)d_in[16];
    const float* cv2_w   = (const float*)d_in[17];
    const float* cv2_b   = (const float*)d_in[18];
    float* out = (float*)d_out;

    gemm_all_kernel<<<400, 64>>>(x, gate_w, gate_b,
                                 wk_cmp, wv_cmp, wk_slc, wv_slc, wk_win, wv_win);
    summarize_kernel<<<dim3(NB, 2), 512>>>(blockp,
                                           ck1_w, ck1_b, ck2_w, ck2_b,
                                           cv1_w, cv1_b, cv2_w, cv2_b);
    cmp_kernel<<<dim3(TT, NKV), 128>>>(q);
    slc_kernel<<<dim3(TT, NKV), 256>>>(q);
    win_final_kernel<<<dim3(TT, NKV), 256>>>(q, out);
}

// round 12
// speedup vs baseline: 1.9802x; 1.6611x over previous
#include <cuda_runtime.h>
#include <math.h>

#define TT   1024
#define DM   1024
#define NQ   16
#define NKV  4
#define DH   64
#define NB   63
#define TOPN 8
#define WIN  256
#define SCALE 0.125f

typedef unsigned long long ull;

// packed fp32x2 FMA: d = a*b + d  (per 32-bit half) -> SASS FFMA2
#define FMA2(d, a, b)  asm("fma.rn.f32x2 %0, %1, %2, %0;" : "+l"(d) : "l"(a), "l"(b))
// duplicate one float into both halves of a b64
#define PACKDUP(d, a)  asm("mov.b64 %0, {%1, %1};" : "=l"(d) : "f"(a))
// pack two floats into a b64
#define PACK2(d, x, y) asm("mov.b64 %0, {%1, %2};" : "=l"(d) : "f"(x), "f"(y))

// ---------------- scratch (device globals; no allocation) ----------------
__device__ float g_gates[TT * 48];
__device__ float g_kc[TT * 256];
__device__ float g_vc[TT * 256];
__device__ float g_vs[TT * 256];
__device__ float g_vw[TT * 256];
// K tensors stored quad-transposed: KT[kv][quad][pos] as float4 = dims 4q..4q+3 of pos
__device__ float4 g_ksT[NKV * 16 * TT];
__device__ float4 g_kwT[NKV * 16 * TT];
__device__ float4 g_ksumT[NKV * 16 * 64];   // [kv][quad][block], padded to 64 blocks
__device__ float g_vsum[NB * 256];
__device__ float g_outcmp[NQ * TT * DH];
__device__ float g_outslc[NQ * TT * DH];
__device__ int   g_sel[NKV * TT * TOPN];

// ================= fused GEMM: 6 projections + gates, f32x2, 128 threads =================
// 64x64 tile, thread microtile 8m x 4n (4 m-pair ull accs x 4 n).
// Epilogue goes through a smem transpose tile -> all global stores coalesced STG.128.
__global__ __launch_bounds__(128) void gemm_all_kernel(
    const float* __restrict__ x,
    const float* __restrict__ gate_w, const float* __restrict__ gate_b,
    const float* __restrict__ wkc, const float* __restrict__ wvc,
    const float* __restrict__ wks, const float* __restrict__ wvs,
    const float* __restrict__ wkw, const float* __restrict__ wvw)
{
    __shared__ float As[16][64];
    __shared__ float Bs[16][64];
    __shared__ float Ct[64][68];             // transpose tile, pad 68 (16B-aligned rows)

    const int b = blockIdx.x;
    const float* Bw;
    float* C = 0;
    float* KT = 0;
    int Nn, ldc = 256, m0, n0;
    bool gate = false;
    if (b < 384) {
        const int tz = b >> 6, rem = b & 63;
        switch (tz) {
            case 0: Bw = wkc; C = g_kc; break;
            case 1: Bw = wvc; C = g_vc; break;
            case 2: Bw = wks; KT = (float*)g_ksT; break;
            case 3: Bw = wvs; C = g_vs; break;
            case 4: Bw = wkw; KT = (float*)g_kwT; break;
            default: Bw = wvw; C = g_vw; break;
        }
        m0 = (rem >> 2) * 64; n0 = (rem & 3) * 64; Nn = 256;
    } else {
        Bw = gate_w; C = g_gates;
        m0 = (b - 384) * 64; n0 = 0; Nn = 48; ldc = 48; gate = true;
    }

    const int tid = threadIdx.x;
    const int tx = tid & 15, ty = tid >> 4;   // n = tx*4, m = ty*8

    ull acc[4][4];                            // [m-pair][n]
#pragma unroll
    for (int i = 0; i < 4; i++)
#pragma unroll
        for (int j = 0; j < 4; j++) acc[i][j] = 0ull;

    for (int k0 = 0; k0 < DM; k0 += 16) {
#pragma unroll
        for (int i = 0; i < 2; i++) {
            const int idx = tid + i * 128;    // lane-consecutive float4 -> coalesced
            const int row = idx >> 2, c4 = (idx & 3) << 2;
            float4 av = *(const float4*)(x + (m0 + row) * DM + k0 + c4);
            As[c4 + 0][row] = av.x; As[c4 + 1][row] = av.y;
            As[c4 + 2][row] = av.z; As[c4 + 3][row] = av.w;
            float4 bv = make_float4(0.f, 0.f, 0.f, 0.f);
            const int n = n0 + row;
            if (n < Nn) bv = *(const float4*)(Bw + n * DM + k0 + c4);
            Bs[c4 + 0][row] = bv.x; Bs[c4 + 1][row] = bv.y;
            Bs[c4 + 2][row] = bv.z; Bs[c4 + 3][row] = bv.w;
        }
        __syncthreads();
#pragma unroll
        for (int kk = 0; kk < 16; kk++) {
            // A: 8 consecutive m -> 4 ull pairs, loaded directly (m-contiguous in As)
            float4 af0 = *(const float4*)&As[kk][ty * 8];
            float4 af1 = *(const float4*)&As[kk][ty * 8 + 4];
            ull a4[4];
            PACK2(a4[0], af0.x, af0.y); PACK2(a4[1], af0.z, af0.w);
            PACK2(a4[2], af1.x, af1.y); PACK2(a4[3], af1.z, af1.w);
            // B: 4 n values, dup'd
            float4 bf = *(const float4*)&Bs[kk][tx * 4];
            ull b0, b1, b2, b3;
            PACKDUP(b0, bf.x); PACKDUP(b1, bf.y); PACKDUP(b2, bf.z); PACKDUP(b3, bf.w);
#pragma unroll
            for (int mp = 0; mp < 4; mp++) {
                FMA2(acc[mp][0], a4[mp], b0);
                FMA2(acc[mp][1], a4[mp], b1);
                FMA2(acc[mp][2], a4[mp], b2);
                FMA2(acc[mp][3], a4[mp], b3);
            }
        }
        __syncthreads();
    }

    // scatter accumulators into smem tile (one-time)
#pragma unroll
    for (int mp = 0; mp < 4; mp++)
#pragma unroll
        for (int j = 0; j < 4; j++) {
            union { ull u; float2 f; } cv; cv.u = acc[mp][j];
            Ct[ty * 8 + 2 * mp + 0][tx * 4 + j] = cv.f.x;
            Ct[ty * 8 + 2 * mp + 1][tx * 4 + j] = cv.f.y;
        }
    __syncthreads();

    if (KT) {
        // quad-transposed output: for each quad q, 64 consecutive float4 (m) -> coalesced
        const int kv = n0 >> 6;
        const int m = tid & 63;
        const int qh = tid >> 6;              // 0 or 1
#pragma unroll
        for (int pass = 0; pass < 8; pass++) {
            const int qd = pass * 2 + qh;
            float4 v = *(const float4*)&Ct[m][qd * 4];
            ((float4*)KT)[(kv * 16 + qd) * TT + m0 + m] = v;
        }
    } else {
        // row-major coalesced: thread covers rows tid>>2 (+32), 16-col chunk tid&3
#pragma unroll
        for (int p = 0; p < 2; p++) {
            const int m = (tid >> 2) + p * 32;
            const int c0 = (tid & 3) * 16;
#pragma unroll
            for (int j = 0; j < 4; j++) {
                const int n = c0 + j * 4;
                if (n < Nn) {
                    float4 v = *(const float4*)&Ct[m][n];
                    if (gate) {
                        v.x = 1.f / (1.f + expf(-(v.x + gate_b[n + 0])));
                        v.y = 1.f / (1.f + expf(-(v.y + gate_b[n + 1])));
                        v.z = 1.f / (1.f + expf(-(v.z + gate_b[n + 2])));
                        v.w = 1.f / (1.f + expf(-(v.w + gate_b[n + 3])));
                    }
                    *(float4*)(C + (m0 + m) * ldc + n0 + n) = v;
                }
            }
        }
    }
}

// ================= block summaries: MLP(2048->64->64), k+v fused, kv-reuse =================
__global__ __launch_bounds__(512) void summarize_kernel(
    const float* __restrict__ bp,
    const float* __restrict__ ck1w, const float* __restrict__ ck1b,
    const float* __restrict__ ck2w, const float* __restrict__ ck2b,
    const float* __restrict__ cv1w, const float* __restrict__ cv1b,
    const float* __restrict__ cv2w, const float* __restrict__ cv2b)
{
    const int n = blockIdx.x, path = blockIdx.y;
    const float* src = path ? g_vc : g_kc;
    const float* w1  = path ? cv1w : ck1w;
    const float* b1  = path ? cv1b : ck1b;
    const float* w2  = path ? cv2w : ck2w;
    const float* b2  = path ? cv2b : ck2b;

    __shared__ float flat[4][2048];
    __shared__ float hid[4][64];
    const int tid = threadIdx.x, warp = tid >> 5, lane = tid & 31;
    const int t0 = n * 16;

    for (int idx = tid; idx < 8192; idx += 512) {
        const int t = idx >> 8, c = idx & 255;
        flat[c >> 6][t * 64 + (c & 63)] = src[(t0 + t) * 256 + c] + bp[t * 64 + (c & 63)];
    }
    __syncthreads();

    float s[4][4];
#pragma unroll
    for (int oo = 0; oo < 4; oo++)
#pragma unroll
        for (int kv = 0; kv < 4; kv++) s[oo][kv] = 0.f;

    const float4* w1r0 = (const float4*)(w1 + (warp * 4 + 0) * 2048);
    const float4* w1r1 = (const float4*)(w1 + (warp * 4 + 1) * 2048);
    const float4* w1r2 = (const float4*)(w1 + (warp * 4 + 2) * 2048);
    const float4* w1r3 = (const float4*)(w1 + (warp * 4 + 3) * 2048);

#pragma unroll 4
    for (int c = 0; c < 16; c++) {
        const int off = lane + c * 32;
        float4 wv[4];
        wv[0] = w1r0[off]; wv[1] = w1r1[off]; wv[2] = w1r2[off]; wv[3] = w1r3[off];
#pragma unroll
        for (int kv = 0; kv < 4; kv++) {
            const float4 fv = ((const float4*)flat[kv])[off];
#pragma unroll
            for (int oo = 0; oo < 4; oo++)
                s[oo][kv] += wv[oo].x * fv.x + wv[oo].y * fv.y + wv[oo].z * fv.z + wv[oo].w * fv.w;
        }
    }
#pragma unroll
    for (int oo = 0; oo < 4; oo++)
#pragma unroll
        for (int kv = 0; kv < 4; kv++)
            for (int off = 16; off; off >>= 1)
                s[oo][kv] += __shfl_xor_sync(0xffffffffu, s[oo][kv], off);

    if (lane == 0) {
#pragma unroll
        for (int oo = 0; oo < 4; oo++) {
            const int o = warp * 4 + oo;
#pragma unroll
            for (int kv = 0; kv < 4; kv++) {
                float g = s[oo][kv] + b1[o];
                hid[kv][o] = 0.5f * g * (1.f + erff(g * 0.7071067811865476f));  // exact gelu
            }
        }
    }
    __syncthreads();

    if (tid < 256) {
        const int kv = tid >> 6, o = tid & 63;
        const float4* w2r = (const float4*)(w2 + o * 64);
        const float4* h4  = (const float4*)hid[kv];
        float s2 = b2[o];
#pragma unroll
        for (int c = 0; c < 16; c++) {
            float4 wv = w2r[c], hv = h4[c];
            s2 += wv.x * hv.x + wv.y * hv.y + wv.z * hv.z + wv.w * hv.w;
        }
        if (path)
            g_vsum[n * 256 + kv * 64 + o] = s2;
        else
            ((float*)g_ksumT)[(((kv * 16 + (o >> 2)) * 64 + n) << 2) + (o & 3)] = s2;
    }
}

// ================= compressed attention + importance + warp-parallel top-8 =================
__global__ __launch_bounds__(128) void cmp_kernel(const float* __restrict__ q)
{
    const int t = blockIdx.x, kv = blockIdx.y;
    const int tid = threadIdx.x;            // 128 threads = 4 warps
    const int warp = tid >> 5, lane = tid & 31;
    __shared__ float4 qs4[4][16];
    __shared__ float p[4][64];
    __shared__ float impS[64];

    if (tid < 64) {
        int r = tid >> 4, c = tid & 15;
        qs4[r][c] = ((const float4*)(q + ((r * NKV + kv) * TT + t) * DH))[c];
    }
    __syncthreads();

    const int nvis = (t >= 31) ? (((t - 31) >> 4) + 1) : 0;  // fully-past blocks

    const int n0 = lane, n1 = lane + 32;
    float d0 = -1e30f, d1 = -1e30f;
    {
        float a0 = 0.f, a1 = 0.f;
#pragma unroll
        for (int c = 0; c < 16; c++) {
            float4 qq = qs4[warp][c];
            float4 k0 = g_ksumT[(kv * 16 + c) * 64 + n0];     // lanes consecutive -> coalesced
            a0 += qq.x * k0.x + qq.y * k0.y + qq.z * k0.z + qq.w * k0.w;
            if (n1 < NB) {
                float4 k1 = g_ksumT[(kv * 16 + c) * 64 + n1];
                a1 += qq.x * k1.x + qq.y * k1.y + qq.z * k1.z + qq.w * k1.w;
            }
        }
        if (n0 < nvis) d0 = a0 * SCALE;
        if (n1 < NB && n1 < nvis) d1 = a1 * SCALE;
    }
    if (nvis == 0) {
        p[warp][n0] = 1.f / 63.f;
        if (n1 < NB) p[warp][n1] = 1.f / 63.f;
    } else {
        float m = fmaxf(d0, d1);
        for (int o = 16; o; o >>= 1) m = fmaxf(m, __shfl_xor_sync(0xffffffffu, m, o));
        float e0 = (n0 < nvis) ? expf(d0 - m) : 0.f;
        float e1 = (n1 < NB && n1 < nvis) ? expf(d1 - m) : 0.f;
        float s = e0 + e1;
        for (int o = 16; o; o >>= 1) s += __shfl_xor_sync(0xffffffffu, s, o);
        float inv = 1.f / s;
        p[warp][n0] = e0 * inv;
        if (n1 < NB) p[warp][n1] = e1 * inv;
    }
    __syncthreads();

    if (tid < NB) impS[tid] = p[0][tid] + p[1][tid] + p[2][tid] + p[3][tid];

    for (int i = tid; i < 256; i += 128) {
        int r = i >> 6, d = i & 63;
        float a = 0.f;
        for (int nn = 0; nn < nvis; nn++) a += p[r][nn] * g_vsum[nn * 256 + kv * 64 + d];
        g_outcmp[((r * NKV + kv) * TT + t) * DH + d] = a;
    }
    __syncthreads();

    // warp-parallel top-8: argmax w/ lowest-index tie-break == serial strict-> scan
    if (warp == 0) {
        float v0 = (n0 < NB) ? impS[n0] : -2.f;
        float v1 = (n1 < NB) ? impS[n1] : -2.f;
#pragma unroll
        for (int it = 0; it < TOPN; it++) {
            float cv = v0; int ci = n0;
            if (v1 > cv) { cv = v1; ci = n1; }
            for (int off = 16; off; off >>= 1) {
                float ov = __shfl_xor_sync(0xffffffffu, cv, off);
                int   oi = __shfl_xor_sync(0xffffffffu, ci, off);
                if (ov > cv || (ov == cv && oi < ci)) { cv = ov; ci = oi; }
            }
            if (lane == 0) g_sel[(kv * TT + t) * TOPN + it] = ci;
            if (n0 == ci) v0 = -2.f;
            if (n1 == ci) v1 = -2.f;
        }
    }
}

// ===== 3-barrier softmax; probs written packed across heads: scp[pos] = (p0,p1,p2,p3) =====
__device__ __forceinline__ void softmax4_pack(float (&val)[4], float4* scp,
                                              float (&redm)[4][8], float (&reds)[4][8],
                                              int tid, int warp, int lane)
{
#pragma unroll
    for (int r = 0; r < 4; r++) {
        float m = val[r];
        for (int o = 16; o; o >>= 1) m = fmaxf(m, __shfl_xor_sync(0xffffffffu, m, o));
        if (lane == 0) redm[r][warp] = m;
    }
    __syncthreads();
    float e[4];
#pragma unroll
    for (int r = 0; r < 4; r++) {
        float m = redm[r][0];
#pragma unroll
        for (int w = 1; w < 8; w++) m = fmaxf(m, redm[r][w]);
        e[r] = expf(val[r] - m);
        float s = e[r];
        for (int o = 16; o; o >>= 1) s += __shfl_xor_sync(0xffffffffu, s, o);
        if (lane == 0) reds[r][warp] = s;
    }
    __syncthreads();
    float iv[4];
#pragma unroll
    for (int r = 0; r < 4; r++) {
        float s = reds[r][0];
#pragma unroll
        for (int w = 1; w < 8; w++) s += reds[r][w];
        iv[r] = e[r] / s;
    }
    scp[tid] = make_float4(iv[0], iv[1], iv[2], iv[3]);
    __syncthreads();
}

// ================= selected-blocks attention =================
__global__ __launch_bounds__(256) void slc_kernel(const float* __restrict__ q)
{
    const int t = blockIdx.x, kv = blockIdx.y, tid = threadIdx.x;
    const int warp = tid >> 5, lane = tid & 31;
    __shared__ float4 qs4[4][16];
    __shared__ float4 scp[256];
    __shared__ int   pos[256];
    __shared__ float redm[4][8], reds[4][8];
    __shared__ float4 part[4][16][17];

    if (tid < 64) {
        int r = tid >> 4, c = tid & 15;
        qs4[r][c] = ((const float4*)(q + ((r * NKV + kv) * TT + t) * DH))[c];
    }
    {
        int blk = g_sel[(kv * TT + t) * TOPN + (tid >> 5)];
        pos[tid] = blk * 16 + (tid & 31);    // starts[blk] + offset, always < T; warp-contiguous
    }
    __syncthreads();

    const int ps = pos[tid];
    const bool valid = (ps <= t);
    float val[4];
    if (valid) {
        float acc[4] = {0.f, 0.f, 0.f, 0.f};
        const float4* kt = g_ksT + kv * 16 * TT + ps;
#pragma unroll
        for (int c = 0; c < 16; c++) {
            float4 kk = kt[c * TT];          // lanes = consecutive ps -> coalesced
#pragma unroll
            for (int r = 0; r < 4; r++) {
                float4 qq = qs4[r][c];
                acc[r] += qq.x * kk.x + qq.y * kk.y + qq.z * kk.z + qq.w * kk.w;
            }
        }
#pragma unroll
        for (int r = 0; r < 4; r++) val[r] = acc[r] * SCALE;
    } else {
#pragma unroll
        for (int r = 0; r < 4; r++) val[r] = -1e30f;
    }

    softmax4_pack(val, scp, redm, reds, tid, warp, lane);

    // AV: V row-major, (sub,dq) mapping -> coalesced; V loaded once, shared by 4 heads
    const int sub = tid >> 4, dq = tid & 15;
    float4 a0 = make_float4(0,0,0,0), a1 = a0, a2 = a0, a3 = a0;
#pragma unroll 4
    for (int i = 0; i < 16; i++) {
        const int s2 = sub * 16 + i;
        const float4 vv = *(const float4*)(g_vs + pos[s2] * 256 + kv * 64 + dq * 4);
        const float4 pp = scp[s2];
        a0.x += pp.x * vv.x; a0.y += pp.x * vv.y; a0.z += pp.x * vv.z; a0.w += pp.x * vv.w;
        a1.x += pp.y * vv.x; a1.y += pp.y * vv.y; a1.z += pp.y * vv.z; a1.w += pp.y * vv.w;
        a2.x += pp.z * vv.x; a2.y += pp.z * vv.y; a2.z += pp.z * vv.z; a2.w += pp.z * vv.w;
        a3.x += pp.w * vv.x; a3.y += pp.w * vv.y; a3.z += pp.w * vv.z; a3.w += pp.w * vv.w;
    }
    part[0][sub][dq] = a0; part[1][sub][dq] = a1;
    part[2][sub][dq] = a2; part[3][sub][dq] = a3;
    __syncthreads();
    if (tid < 64) {
        const int r = tid >> 4, dq2 = tid & 15;
        float4 s = make_float4(0,0,0,0);
#pragma unroll
        for (int u = 0; u < 16; u++) {
            float4 pv = part[r][u][dq2];
            s.x += pv.x; s.y += pv.y; s.z += pv.z; s.w += pv.w;
        }
        ((float4*)(g_outslc + ((r * NKV + kv) * TT + t) * DH))[dq2] = s;
    }
}

// ================= sliding window attention + gating + final output =================
__global__ __launch_bounds__(256) void win_final_kernel(const float* __restrict__ q,
                                                        float* __restrict__ out)
{
    const int t = blockIdx.x, kv = blockIdx.y, tid = threadIdx.x;
    const int warp = tid >> 5, lane = tid & 31;
    __shared__ float4 qs4[4][16];
    __shared__ float4 scp[256];
    __shared__ float redm[4][8], reds[4][8];
    __shared__ float4 part[4][16][17];

    const int j0 = (t >= WIN - 1) ? t - (WIN - 1) : 0;
    const int nj = t - j0 + 1;

    if (tid < 64) {
        int r = tid >> 4, c = tid & 15;
        qs4[r][c] = ((const float4*)(q + ((r * NKV + kv) * TT + t) * DH))[c];
    }
    __syncthreads();

    const bool valid = (tid < nj);
    float val[4];
    if (valid) {
        float acc[4] = {0.f, 0.f, 0.f, 0.f};
        const float4* kt = g_kwT + kv * 16 * TT + (j0 + tid);
#pragma unroll
        for (int c = 0; c < 16; c++) {
            float4 kk = kt[c * TT];          // lanes consecutive -> coalesced
#pragma unroll
            for (int r = 0; r < 4; r++) {
                float4 qq = qs4[r][c];
                acc[r] += qq.x * kk.x + qq.y * kk.y + qq.z * kk.z + qq.w * kk.w;
            }
        }
#pragma unroll
        for (int r = 0; r < 4; r++) val[r] = acc[r] * SCALE;
    } else {
#pragma unroll
        for (int r = 0; r < 4; r++) val[r] = -1e30f;
    }

    softmax4_pack(val, scp, redm, reds, tid, warp, lane);

    const int sub = tid >> 4, dq = tid & 15;
    float4 a0 = make_float4(0,0,0,0), a1 = a0, a2 = a0, a3 = a0;
#pragma unroll 4
    for (int i = 0; i < 16; i++) {
        const int s2 = sub * 16 + i;
        const float4 vv = *(const float4*)(g_vw + (j0 + s2) * 256 + kv * 64 + dq * 4);
        const float4 pp = scp[s2];
        a0.x += pp.x * vv.x; a0.y += pp.x * vv.y; a0.z += pp.x * vv.z; a0.w += pp.x * vv.w;
        a1.x += pp.y * vv.x; a1.y += pp.y * vv.y; a1.z += pp.y * vv.z; a1.w += pp.y * vv.w;
        a2.x += pp.z * vv.x; a2.y += pp.z * vv.y; a2.z += pp.z * vv.z; a2.w += pp.z * vv.w;
        a3.x += pp.w * vv.x; a3.y += pp.w * vv.y; a3.z += pp.w * vv.z; a3.w += pp.w * vv.w;
    }
    part[0][sub][dq] = a0; part[1][sub][dq] = a1;
    part[2][sub][dq] = a2; part[3][sub][dq] = a3;
    __syncthreads();
    if (tid < 64) {
        const int r = tid >> 4, dq2 = tid & 15;
        float4 s = make_float4(0,0,0,0);
#pragma unroll
        for (int u = 0; u < 16; u++) {
            float4 pv = part[r][u][dq2];
            s.x += pv.x; s.y += pv.y; s.z += pv.z; s.w += pv.w;
        }
        const int h = r * NKV + kv;
        const float g0 = g_gates[t * 48 + h * 3 + 0];
        const float g1 = g_gates[t * 48 + h * 3 + 1];
        const float g2 = g_gates[t * 48 + h * 3 + 2];
        const int obase = (h * TT + t) * DH;
        float4 oc = ((const float4*)(g_outcmp + obase))[dq2];
        float4 os = ((const float4*)(g_outslc + obase))[dq2];
        float4 res;
        res.x = g0 * oc.x + g1 * os.x + g2 * s.x;
        res.y = g0 * oc.y + g1 * os.y + g2 * s.y;
        res.z = g0 * oc.z + g1 * os.z + g2 * s.z;
        res.w = g0 * oc.w + g1 * os.w + g2 * s.w;
        ((float4*)(out + obase))[dq2] = res;
    }
}

// ---------------- launch ----------------
extern "C" void kernel_launch(void* const* d_in, const int* in_sizes, int n_in,
                              void* d_out, int out_size)
{
    (void)in_sizes; (void)n_in; (void)out_size;
    const float* x       = (const float*)d_in[0];
    const float* q       = (const float*)d_in[1];
    const float* gate_w  = (const float*)d_in[2];
    const float* gate_b  = (const float*)d_in[3];
    const float* wk_cmp  = (const float*)d_in[4];
    const float* wv_cmp  = (const float*)d_in[5];
    const float* wk_slc  = (const float*)d_in[6];
    const float* wv_slc  = (const float*)d_in[7];
    const float* wk_win  = (const float*)d_in[8];
    const float* wv_win  = (const float*)d_in[9];
    const float* blockp  = (const float*)d_in[10];
    const float* ck1_w   = (const float*)d_in[11];
    const float* ck1_b   = (const float*)d_in[12];
    const float* ck2_w   = (const float*)d_in[13];
    const float* ck2_b   = (const float*)d_in[14];
    const float* cv1_w   = (const float*)d_in[15];
    const float* cv1_b   = (const float*)d_in[16];
    const float* cv2_w   = (const float*)d_in[17];
    const float* cv2_b   = (const float*)d_in[18];
    float* out = (float*)d_out;

    gemm_all_kernel<<<400, 128>>>(x, gate_w, gate_b,
                                  wk_cmp, wv_cmp, wk_slc, wv_slc, wk_win, wv_win);
    summarize_kernel<<<dim3(NB, 2), 512>>>(blockp,
                                           ck1_w, ck1_b, ck2_w, ck2_b,
                                           cv1_w, cv1_b, cv2_w, cv2_b);
    cmp_kernel<<<dim3(TT, NKV), 128>>>(q);
    slc_kernel<<<dim3(TT, NKV), 256>>>(q);
    win_final_kernel<<<dim3(TT, NKV), 256>>>(q, out);
}